// round 3
// baseline (speedup 1.0000x reference)
#include <cuda_runtime.h>

// ---------------------------------------------------------------------------
// DFMNET: 2-layer LSTM (B=2048, T=256, I=64, H=128) + 6-layer MLP head.
// Strategy: recurrence is independent per batch row -> persistent CTA per
// 16-row batch tile runs all 256 timesteps with state in smem/registers.
// GEMMs use packed fp32x2 FMA (2 rows per 64-bit lane pair) to hit the full
// 128 FMA/cyc/SM fp32 rate on sm_103a. Weights repacked once per launch into
// fused k-major layout for coalesced, prefetchable loads (served from L2).
// ---------------------------------------------------------------------------

#define T_SEQ    256
#define I_IN     64
#define H_HID    128
#define G4       512          // 4*H gates
#define ROWS     16           // batch rows per CTA
#define SROW     20           // padded row-stride in smem (16 rows + 4 pad, 16B aligned)
#define NTHREADS 256
#define KROWS    320          // fused activation buffer rows: [x(64) | h1(128) | h2(128)]

// Repacked weights (built by prep_kernel each launch; deterministic).
__device__ float g_Wt1[192 * 512];   // layer1: k-major [k][gate], k = concat(x, h1)
__device__ float g_Wt2[256 * 512];   // layer2: k-major [k][gate], k = concat(h1, h2)
__device__ float g_b1[512];          // b_ih1 + b_hh1
__device__ float g_b2[512];          // b_ih2 + b_hh2

typedef unsigned long long ull;

// ---- packed fp32x2 helpers (sm_100+ PTX; ptxas will not emit these from C++) ----
__device__ __forceinline__ ull pack2(float w) {
    ull r; unsigned u = __float_as_uint(w);
    asm("mov.b64 %0, {%1, %1};" : "=l"(r) : "r"(u));
    return r;
}
__device__ __forceinline__ ull fma2(ull a, ull b, ull c) {
    ull d;
    asm("fma.rn.f32x2 %0, %1, %2, %3;" : "=l"(d) : "l"(a), "l"(b), "l"(c));
    return d;
}
__device__ __forceinline__ void unpack2(ull v, float& lo, float& hi) {
    unsigned a, b;
    asm("mov.b64 {%0, %1}, %2;" : "=r"(a), "=r"(b) : "l"(v));
    lo = __uint_as_float(a); hi = __uint_as_float(b);
}

__device__ __forceinline__ float sigf(float v) {
    return __fdividef(1.f, 1.f + __expf(-v));
}
__device__ __forceinline__ float tanhf_fast(float v) {
    float z = fminf(fmaxf(v, -15.f), 15.f);   // clamp avoids inf/inf NaN
    float e = __expf(-2.f * z);
    return __fdividef(1.f - e, 1.f + e);
}

// ---------------------------------------------------------------------------
// Weight repack: fuse (W_ih | W_hh) and transpose to k-major [K][512].
// ---------------------------------------------------------------------------
__global__ void prep_kernel(const float* __restrict__ Wih1, const float* __restrict__ Whh1,
                            const float* __restrict__ bih1, const float* __restrict__ bhh1,
                            const float* __restrict__ Wih2, const float* __restrict__ Whh2,
                            const float* __restrict__ bih2, const float* __restrict__ bhh2)
{
    int tid = blockIdx.x * blockDim.x + threadIdx.x;
    int stride = gridDim.x * blockDim.x;
    if (tid < 512) {
        g_b1[tid] = bih1[tid] + bhh1[tid];
        g_b2[tid] = bih2[tid] + bhh2[tid];
    }
    for (int e = tid; e < 192 * 512; e += stride) {
        int k = e >> 9, g = e & 511;
        g_Wt1[e] = (k < 64) ? Wih1[g * 64 + k] : Whh1[g * 128 + (k - 64)];
    }
    for (int e = tid; e < 256 * 512; e += stride) {
        int k = e >> 9, g = e & 511;
        g_Wt2[e] = (k < 128) ? Wih2[g * 128 + k] : Whh2[g * 128 + (k - 128)];
    }
}

// ---------------------------------------------------------------------------
// Per-step gate GEMM: gates[16][512] = bias + xh[16][K] @ Wt[K][512]
// Thread owns 2 gate columns (g0=tid, g1=tid+256) x all 16 rows, rows packed
// in pairs into f32x2 accumulators. xh is k-major in smem: xh[k][SROW].
// Weight loads are coalesced (consecutive threads -> consecutive gates) and
// double-buffered across k-chunks to hide L2 latency.
// ---------------------------------------------------------------------------
__device__ __forceinline__ void gemm_gates(const float* __restrict__ Wt,
                                           const float* __restrict__ bias,
                                           const float* __restrict__ xh,
                                           float* __restrict__ gates,
                                           int K, int tid)
{
    const int g0 = tid;
    const int g1 = tid + 256;

    ull acc0[8], acc1[8];
    {
        ull b0p = pack2(bias[g0]), b1p = pack2(bias[g1]);
#pragma unroll
        for (int p = 0; p < 8; p++) { acc0[p] = b0p; acc1[p] = b1p; }
    }

    float w0[4], w1[4];
#pragma unroll
    for (int j = 0; j < 4; j++) { w0[j] = Wt[j * 512 + g0]; w1[j] = Wt[j * 512 + g1]; }

    for (int k = 0; k < K; k += 4) {
        float n0[4], n1[4];
        int kn = k + 4;
        if (kn < K) {
#pragma unroll
            for (int j = 0; j < 4; j++) {
                n0[j] = Wt[(kn + j) * 512 + g0];
                n1[j] = Wt[(kn + j) * 512 + g1];
            }
        } else {
#pragma unroll
            for (int j = 0; j < 4; j++) { n0[j] = 0.f; n1[j] = 0.f; }
        }
#pragma unroll
        for (int j = 0; j < 4; j++) {
            ull w0p = pack2(w0[j]);
            ull w1p = pack2(w1[j]);
            // 16 rows for this k: 64 contiguous bytes (broadcast across warp)
            const ulonglong2* xr = (const ulonglong2*)(xh + (k + j) * SROW);
            ulonglong2 q0 = xr[0];
            ulonglong2 q1 = xr[1];
            ulonglong2 q2 = xr[2];
            ulonglong2 q3 = xr[3];
            acc0[0] = fma2(w0p, q0.x, acc0[0]);  acc1[0] = fma2(w1p, q0.x, acc1[0]);
            acc0[1] = fma2(w0p, q0.y, acc0[1]);  acc1[1] = fma2(w1p, q0.y, acc1[1]);
            acc0[2] = fma2(w0p, q1.x, acc0[2]);  acc1[2] = fma2(w1p, q1.x, acc1[2]);
            acc0[3] = fma2(w0p, q1.y, acc0[3]);  acc1[3] = fma2(w1p, q1.y, acc1[3]);
            acc0[4] = fma2(w0p, q2.x, acc0[4]);  acc1[4] = fma2(w1p, q2.x, acc1[4]);
            acc0[5] = fma2(w0p, q2.y, acc0[5]);  acc1[5] = fma2(w1p, q2.y, acc1[5]);
            acc0[6] = fma2(w0p, q3.x, acc0[6]);  acc1[6] = fma2(w1p, q3.x, acc1[6]);
            acc0[7] = fma2(w0p, q3.y, acc0[7]);  acc1[7] = fma2(w1p, q3.y, acc1[7]);
        }
#pragma unroll
        for (int j = 0; j < 4; j++) { w0[j] = n0[j]; w1[j] = n1[j]; }
    }

#pragma unroll
    for (int p = 0; p < 8; p++) {
        float lo, hi;
        unpack2(acc0[p], lo, hi);
        gates[(2 * p) * 512 + g0]     = lo;
        gates[(2 * p + 1) * 512 + g0] = hi;
        unpack2(acc1[p], lo, hi);
        gates[(2 * p) * 512 + g1]     = lo;
        gates[(2 * p + 1) * 512 + g1] = hi;
    }
}

// Small MLP layer over the CTA's 16 rows: vout[r][o] = act(b[o] + W[o,:].vin[r,:])
__device__ __forceinline__ void mlp_layer(const float* __restrict__ vin, int Din,
                                          const float* __restrict__ W, const float* __restrict__ b,
                                          float* __restrict__ vout, int Dout, bool relu, int tid)
{
    for (int e = tid; e < ROWS * Dout; e += NTHREADS) {
        int r = e / Dout, o = e - r * Dout;
        const float* w = W + o * Din;
        const float* vi = vin + r * Din;
        float s = b[o];
        for (int i = 0; i < Din; i += 4) {
            s += w[i] * vi[i] + w[i + 1] * vi[i + 1] + w[i + 2] * vi[i + 2] + w[i + 3] * vi[i + 3];
        }
        vout[e] = relu ? fmaxf(s, 0.f) : s;
    }
    __syncthreads();
}

// ---------------------------------------------------------------------------
// Main persistent kernel: one CTA per 16 batch rows, all T timesteps.
// smem: xh[320][SROW] fused activation buffer (x | h1 | h2, k-major, transposed)
//       gates[16][512] gate scratch (reused as MLP buffers at the end)
// ---------------------------------------------------------------------------
__global__ void __launch_bounds__(NTHREADS, 1)
dfmnet_main(const float* __restrict__ x,
            const float* __restrict__ Wk0, const float* __restrict__ bk0,
            const float* __restrict__ Wk1, const float* __restrict__ bk1,
            const float* __restrict__ Wk2, const float* __restrict__ bk2,
            const float* __restrict__ Wk3, const float* __restrict__ bk3,
            const float* __restrict__ Wk4, const float* __restrict__ bk4,
            const float* __restrict__ Wk5, const float* __restrict__ bk5,
            float* __restrict__ out, int Bn)
{
    extern __shared__ float sm[];
    float* xh    = sm;                      // [KROWS][SROW]
    float* gates = sm + KROWS * SROW;       // [16][512]

    const int tid = threadIdx.x;
    const int b0 = blockIdx.x * ROWS;

    // init: zero h1/h2 regions (zero everything; x region overwritten each step)
    for (int e = tid; e < KROWS * SROW; e += NTHREADS) xh[e] = 0.f;
    float c1r[8], c2r[8];
#pragma unroll
    for (int p = 0; p < 8; p++) { c1r[p] = 0.f; c2r[p] = 0.f; }
    __syncthreads();

    const float* xbase = x + (size_t)b0 * T_SEQ * I_IN;

    for (int t = 0; t < T_SEQ; t++) {
        // load x_t (16 rows x 64) transposed into xh rows [0,64)
#pragma unroll
        for (int q = 0; q < 4; q++) {
            int e = tid + q * NTHREADS;           // 0..1023
            int r = e >> 6, k = e & 63;
            xh[k * SROW + r] = xbase[(size_t)r * (T_SEQ * I_IN) + t * I_IN + k];
        }
        __syncthreads();

        // layer 1: gates = [x | h1_prev] @ Wt1 + b1
        gemm_gates(g_Wt1, g_b1, xh, gates, 192, tid);
        __syncthreads();

        // layer 1 activation; h1 -> xh rows [64,192); c1 in registers
#pragma unroll
        for (int p = 0; p < 8; p++) {
            int idx = tid + p * NTHREADS;         // 0..2047
            int r = idx >> 7, j = idx & 127;
            const float* gr = gates + r * 512 + j;
            float iv = sigf(gr[0]);
            float fv = sigf(gr[128]);
            float gv = tanhf_fast(gr[256]);
            float ov = sigf(gr[384]);
            float c = fv * c1r[p] + iv * gv;
            c1r[p] = c;
            xh[(64 + j) * SROW + r] = ov * tanhf_fast(c);
        }
        __syncthreads();

        // layer 2: gates = [h1 | h2_prev] @ Wt2 + b2  (reads xh rows [64,320))
        gemm_gates(g_Wt2, g_b2, xh + 64 * SROW, gates, 256, tid);
        __syncthreads();

        // layer 2 activation; h2 -> xh rows [192,320); c2 in registers
#pragma unroll
        for (int p = 0; p < 8; p++) {
            int idx = tid + p * NTHREADS;
            int r = idx >> 7, j = idx & 127;
            const float* gr = gates + r * 512 + j;
            float iv = sigf(gr[0]);
            float fv = sigf(gr[128]);
            float gv = tanhf_fast(gr[256]);
            float ov = sigf(gr[384]);
            float c = fv * c2r[p] + iv * gv;
            c2r[p] = c;
            xh[(192 + j) * SROW + r] = ov * tanhf_fast(c);
        }
        // next iteration's x-load touches disjoint smem; its __syncthreads()
        // orders these h2 writes before the next layer-2 GEMM.
    }
    __syncthreads();

    // ---- outputs: tuple (y, h2, r) flattened in order ----
    float* out_y  = out;                              // [Bn][64]
    float* out_h2 = out + (size_t)Bn * 64;            // [Bn][128]
    float* out_r  = out + (size_t)Bn * 192;           // [Bn][192] (offset 64+128)

    // r = concat(h2_final, x[:, T-1, :]); x_{T-1} still resident in xh rows [0,64)
    float* va = gates;              // [16][192]
    float* vb = gates + ROWS * 192; // [16][128]
    float* vc = vb + ROWS * 128;    // [16][128]
    for (int e = tid; e < ROWS * 192; e += NTHREADS) {
        int r = e / 192, j = e - r * 192;
        float v = (j < 128) ? xh[(192 + j) * SROW + r] : xh[(j - 128) * SROW + r];
        va[e] = v;
        out_r[(size_t)(b0 + r) * 192 + j] = v;
        if (j < 128) out_h2[(size_t)(b0 + r) * 128 + j] = v;
    }
    __syncthreads();

    // KDN head: 5x (Linear + ReLU) + final Linear
    mlp_layer(va, 192, Wk0, bk0, vb, 128, true, tid);
    mlp_layer(vb, 128, Wk1, bk1, vc, 128, true, tid);
    mlp_layer(vc, 128, Wk2, bk2, vb, 128, true, tid);
    mlp_layer(vb, 128, Wk3, bk3, vc, 128, true, tid);
    mlp_layer(vc, 128, Wk4, bk4, vb, 128, true, tid);

    for (int e = tid; e < ROWS * 64; e += NTHREADS) {
        int r = e >> 6, o = e & 63;
        const float* w = Wk5 + o * 128;
        const float* vi = vb + r * 128;
        float s = bk5[o];
        for (int i = 0; i < 128; i += 4) {
            s += w[i] * vi[i] + w[i + 1] * vi[i + 1] + w[i + 2] * vi[i + 2] + w[i + 3] * vi[i + 3];
        }
        out_y[(size_t)(b0 + r) * 64 + o] = s;
    }
}

// ---------------------------------------------------------------------------
extern "C" void kernel_launch(void* const* d_in, const int* in_sizes, int n_in,
                              void* d_out, int out_size)
{
    const float* x    = (const float*)d_in[0];
    const float* Wih1 = (const float*)d_in[1];
    const float* Whh1 = (const float*)d_in[2];
    const float* bih1 = (const float*)d_in[3];
    const float* bhh1 = (const float*)d_in[4];
    const float* Wih2 = (const float*)d_in[5];
    const float* Whh2 = (const float*)d_in[6];
    const float* bih2 = (const float*)d_in[7];
    const float* bhh2 = (const float*)d_in[8];
    const float* Wk0 = (const float*)d_in[9];   const float* bk0 = (const float*)d_in[10];
    const float* Wk1 = (const float*)d_in[11];  const float* bk1 = (const float*)d_in[12];
    const float* Wk2 = (const float*)d_in[13];  const float* bk2 = (const float*)d_in[14];
    const float* Wk3 = (const float*)d_in[15];  const float* bk3 = (const float*)d_in[16];
    const float* Wk4 = (const float*)d_in[17];  const float* bk4 = (const float*)d_in[18];
    const float* Wk5 = (const float*)d_in[19];  const float* bk5 = (const float*)d_in[20];

    int Bn = in_sizes[0] / (T_SEQ * I_IN);
    int smem_bytes = (KROWS * SROW + 16 * 512) * (int)sizeof(float);   // 58368 B

    cudaFuncSetAttribute(dfmnet_main, cudaFuncAttributeMaxDynamicSharedMemorySize, smem_bytes);

    prep_kernel<<<208, 256>>>(Wih1, Whh1, bih1, bhh1, Wih2, Whh2, bih2, bhh2);
    dfmnet_main<<<Bn / ROWS, NTHREADS, smem_bytes>>>(
        x, Wk0, bk0, Wk1, bk1, Wk2, bk2, Wk3, bk3, Wk4, bk4, Wk5, bk5,
        (float*)d_out, Bn);
}